// round 2
// baseline (speedup 1.0000x reference)
#include <cuda_runtime.h>
#include <cuda_bf16.h>

#define N_NODES_MAX 100000

// Scratch accumulator + dtype flag (no cudaMalloc allowed).
__device__ float g_local_field[N_NODES_MAX];
__device__ int   g_idx_is64;

// Detect whether edge_index is int64 or int32 (jax silently downcasts
// int64 -> int32 when x64 mode is off). int64 indices < 1e5 have zero
// high 32 bits; int32 data packs two random indices per 8B word, so
// high words are nonzero with overwhelming probability.
__global__ void detect_kernel(const unsigned long long* __restrict__ ei) {
    int is64 = 1;
    for (int i = 0; i < 16; i++) {
        if (ei[i] >> 32) { is64 = 0; break; }
    }
    g_idx_is64 = is64;
}

__global__ void zero_lf_kernel(int n) {
    int i = blockIdx.x * blockDim.x + threadIdx.x;
    if (i < n) g_local_field[i] = 0.0f;
}

// Edge phase: local_field[row] += x[row]*x[col].
// Uniform branch on index dtype; vectorized index loads on both paths.
__global__ void edge_kernel(const float* __restrict__ x,
                            const void* __restrict__ ei,
                            int n_edges) {
    int i = blockIdx.x * blockDim.x + threadIdx.x;
    if (g_idx_is64) {
        int n_pairs = n_edges >> 1;
        if (i >= n_pairs) return;
        const longlong2* rows2 = reinterpret_cast<const longlong2*>(ei);
        const longlong2* cols2 = reinterpret_cast<const longlong2*>(
            reinterpret_cast<const long long*>(ei) + n_edges);
        longlong2 r2 = __ldg(&rows2[i]);
        longlong2 c2 = __ldg(&cols2[i]);
        int r0 = (int)r2.x, r1 = (int)r2.y;
        int c0 = (int)c2.x, c1 = (int)c2.y;
        float v0 = __ldg(&x[r0]) * __ldg(&x[c0]);
        float v1 = __ldg(&x[r1]) * __ldg(&x[c1]);
        atomicAdd(&g_local_field[r0], v0);
        atomicAdd(&g_local_field[r1], v1);
    } else {
        int n_quads = n_edges >> 2;
        if (i >= n_quads) return;
        const int4* rows4 = reinterpret_cast<const int4*>(ei);
        const int4* cols4 = reinterpret_cast<const int4*>(
            reinterpret_cast<const int*>(ei) + n_edges);
        int4 r = __ldg(&rows4[i]);
        int4 c = __ldg(&cols4[i]);
        float v0 = __ldg(&x[r.x]) * __ldg(&x[c.x]);
        float v1 = __ldg(&x[r.y]) * __ldg(&x[c.y]);
        float v2 = __ldg(&x[r.z]) * __ldg(&x[c.z]);
        float v3 = __ldg(&x[r.w]) * __ldg(&x[c.w]);
        atomicAdd(&g_local_field[r.x], v0);
        atomicAdd(&g_local_field[r.y], v1);
        atomicAdd(&g_local_field[r.z], v2);
        atomicAdd(&g_local_field[r.w], v3);
    }
}

// Node MLP: tokens = relu(relu([x, lf] @ w1^T + b1) @ w2^T + b2)
__global__ void mlp_kernel(const float* __restrict__ x,
                           const float* __restrict__ w1,   // [16,2]
                           const float* __restrict__ b1,   // [16]
                           const float* __restrict__ w2,   // [16,16]
                           const float* __restrict__ b2,   // [16]
                           float* __restrict__ out,        // [N,16]
                           int n) {
    __shared__ float s_w1[32];
    __shared__ float s_b1[16];
    __shared__ float s_w2[256];
    __shared__ float s_b2[16];

    int tid = threadIdx.x;
    if (tid < 32)  s_w1[tid] = w1[tid];
    if (tid < 16)  s_b1[tid] = b1[tid];
    if (tid < 256) s_w2[tid] = w2[tid];
    if (tid >= 32 && tid < 48) s_b2[tid - 32] = b2[tid - 32];
    __syncthreads();

    int i = blockIdx.x * blockDim.x + tid;
    if (i >= n) return;

    float xv = x[i];
    float lf = g_local_field[i];

    float h[16];
#pragma unroll
    for (int j = 0; j < 16; j++) {
        float v = fmaf(xv, s_w1[2 * j], fmaf(lf, s_w1[2 * j + 1], s_b1[j]));
        h[j] = fmaxf(v, 0.0f);
    }

    float t[16];
#pragma unroll
    for (int k = 0; k < 16; k++) {
        float acc = s_b2[k];
#pragma unroll
        for (int j = 0; j < 16; j++) {
            acc = fmaf(h[j], s_w2[k * 16 + j], acc);
        }
        t[k] = fmaxf(acc, 0.0f);
    }

    float4* out4 = reinterpret_cast<float4*>(out + (size_t)i * 16);
    out4[0] = make_float4(t[0],  t[1],  t[2],  t[3]);
    out4[1] = make_float4(t[4],  t[5],  t[6],  t[7]);
    out4[2] = make_float4(t[8],  t[9],  t[10], t[11]);
    out4[3] = make_float4(t[12], t[13], t[14], t[15]);
}

extern "C" void kernel_launch(void* const* d_in, const int* in_sizes, int n_in,
                              void* d_out, int out_size) {
    const float* x  = (const float*)d_in[0];
    const void*  ei = d_in[1];                 // [2, E], int64 OR int32
    const float* w1 = (const float*)d_in[2];
    const float* b1 = (const float*)d_in[3];
    const float* w2 = (const float*)d_in[4];
    const float* b2 = (const float*)d_in[5];
    float* out = (float*)d_out;

    int n_nodes = in_sizes[0];          // x is [N,1]
    int n_edges = in_sizes[1] / 2;      // edge_index is [2,E]
    if (n_nodes > N_NODES_MAX) n_nodes = N_NODES_MAX;

    // 0) sniff index dtype
    detect_kernel<<<1, 1>>>((const unsigned long long*)ei);

    // 1) zero accumulator
    {
        int threads = 256;
        int blocks = (n_nodes + threads - 1) / threads;
        zero_lf_kernel<<<blocks, threads>>>(n_nodes);
    }

    // 2) edge scatter — launch enough threads for the int64 path (2 edges/thr);
    //    the int32 path (4 edges/thr) just early-outs the upper half.
    {
        int n_pairs = (n_edges + 1) >> 1;
        int threads = 256;
        int blocks = (n_pairs + threads - 1) / threads;
        edge_kernel<<<blocks, threads>>>(x, ei, n_edges);
    }

    // 3) fused 2-layer MLP
    {
        int threads = 256;
        int blocks = (n_nodes + threads - 1) / threads;
        mlp_kernel<<<blocks, threads>>>(x, w1, b1, w2, b2, out, n_nodes);
    }
}

// round 3
// speedup vs baseline: 1.1657x; 1.1657x over previous
#include <cuda_runtime.h>
#include <cuda_bf16.h>

#define N_NODES_MAX 100000

// Scratch accumulator + dtype flag (no cudaMalloc allowed).
__device__ float g_local_field[N_NODES_MAX];
__device__ int   g_idx_is64;

// MLP weights in constant memory (filled via graph-capturable D2D memcpy).
__constant__ float c_w1[32];    // [16,2] row-major
__constant__ float c_b1[16];
__constant__ float c_w2[256];   // [16,16] row-major
__constant__ float c_b2[16];

// Detect whether edge_index is int64 or int32 (jax silently downcasts
// int64 -> int32 when x64 mode is off). int64 indices < 1e5 have zero
// high 32 bits; int32 data packs two random indices per 8B word.
__global__ void detect_kernel(const unsigned long long* __restrict__ ei) {
    int is64 = 1;
    for (int i = 0; i < 16; i++) {
        if (ei[i] >> 32) { is64 = 0; break; }
    }
    g_idx_is64 = is64;
}

__global__ void zero_lf_kernel(int n) {
    int i = blockIdx.x * blockDim.x + threadIdx.x;
    if (i < n) g_local_field[i] = 0.0f;
}

// Edge phase (refactored): local_field[row] += x[col]   (x[row] factored out,
// applied in the MLP kernel). 8 edges per thread, index loads front-batched.
__global__ void edge_kernel(const float* __restrict__ x,
                            const void* __restrict__ ei,
                            int n_edges) {
    int i = blockIdx.x * blockDim.x + threadIdx.x;
    int base = i * 8;
    if (base >= n_edges) return;

    int r[8], c[8];

    if (g_idx_is64) {
        const longlong2* rows2 = reinterpret_cast<const longlong2*>(ei);
        const longlong2* cols2 = reinterpret_cast<const longlong2*>(
            reinterpret_cast<const long long*>(ei) + n_edges);
        int p = base >> 1;   // longlong2 index
        longlong2 rr0 = __ldg(&rows2[p + 0]);
        longlong2 rr1 = __ldg(&rows2[p + 1]);
        longlong2 rr2 = __ldg(&rows2[p + 2]);
        longlong2 rr3 = __ldg(&rows2[p + 3]);
        longlong2 cc0 = __ldg(&cols2[p + 0]);
        longlong2 cc1 = __ldg(&cols2[p + 1]);
        longlong2 cc2 = __ldg(&cols2[p + 2]);
        longlong2 cc3 = __ldg(&cols2[p + 3]);
        r[0] = (int)rr0.x; r[1] = (int)rr0.y; r[2] = (int)rr1.x; r[3] = (int)rr1.y;
        r[4] = (int)rr2.x; r[5] = (int)rr2.y; r[6] = (int)rr3.x; r[7] = (int)rr3.y;
        c[0] = (int)cc0.x; c[1] = (int)cc0.y; c[2] = (int)cc1.x; c[3] = (int)cc1.y;
        c[4] = (int)cc2.x; c[5] = (int)cc2.y; c[6] = (int)cc3.x; c[7] = (int)cc3.y;
    } else {
        const int4* rows4 = reinterpret_cast<const int4*>(ei);
        const int4* cols4 = reinterpret_cast<const int4*>(
            reinterpret_cast<const int*>(ei) + n_edges);
        int q = base >> 2;   // int4 index
        int4 ra = __ldg(&rows4[q + 0]);
        int4 rb = __ldg(&rows4[q + 1]);
        int4 ca = __ldg(&cols4[q + 0]);
        int4 cb = __ldg(&cols4[q + 1]);
        r[0] = ra.x; r[1] = ra.y; r[2] = ra.z; r[3] = ra.w;
        r[4] = rb.x; r[5] = rb.y; r[6] = rb.z; r[7] = rb.w;
        c[0] = ca.x; c[1] = ca.y; c[2] = ca.z; c[3] = ca.w;
        c[4] = cb.x; c[5] = cb.y; c[6] = cb.z; c[7] = cb.w;
    }

    // Batch the gathers (independent -> high MLP), then fire atomics.
    float v[8];
#pragma unroll
    for (int k = 0; k < 8; k++) v[k] = __ldg(&x[c[k]]);
#pragma unroll
    for (int k = 0; k < 8; k++) atomicAdd(&g_local_field[r[k]], v[k]);
}

// Node MLP: lf = x[i] * sum(x[col]);  tokens = relu(relu([x, lf]W1^T+b1)W2^T+b2)
__global__ void __launch_bounds__(128) mlp_kernel(const float* __restrict__ x,
                                                  float* __restrict__ out,
                                                  int n) {
    int i = blockIdx.x * blockDim.x + threadIdx.x;
    if (i >= n) return;

    float xv = x[i];
    float lf = xv * g_local_field[i];   // factored x[row] applied here

    float h[16];
#pragma unroll
    for (int j = 0; j < 16; j++) {
        float v = fmaf(xv, c_w1[2 * j], fmaf(lf, c_w1[2 * j + 1], c_b1[j]));
        h[j] = fmaxf(v, 0.0f);
    }

    float t[16];
#pragma unroll
    for (int k = 0; k < 16; k++) {
        float acc = c_b2[k];
#pragma unroll
        for (int j = 0; j < 16; j++) {
            acc = fmaf(h[j], c_w2[k * 16 + j], acc);
        }
        t[k] = fmaxf(acc, 0.0f);
    }

    float4* out4 = reinterpret_cast<float4*>(out + (size_t)i * 16);
    out4[0] = make_float4(t[0],  t[1],  t[2],  t[3]);
    out4[1] = make_float4(t[4],  t[5],  t[6],  t[7]);
    out4[2] = make_float4(t[8],  t[9],  t[10], t[11]);
    out4[3] = make_float4(t[12], t[13], t[14], t[15]);
}

extern "C" void kernel_launch(void* const* d_in, const int* in_sizes, int n_in,
                              void* d_out, int out_size) {
    const float* x  = (const float*)d_in[0];
    const void*  ei = d_in[1];                 // [2, E], int64 OR int32
    float* out = (float*)d_out;

    int n_nodes = in_sizes[0];          // x is [N,1]
    int n_edges = in_sizes[1] / 2;      // edge_index is [2,E]
    if (n_nodes > N_NODES_MAX) n_nodes = N_NODES_MAX;

    // Stage weights into constant memory (D2D async copies: graph-capturable).
    cudaMemcpyToSymbolAsync(c_w1, d_in[2], 32  * sizeof(float), 0,
                            cudaMemcpyDeviceToDevice, 0);
    cudaMemcpyToSymbolAsync(c_b1, d_in[3], 16  * sizeof(float), 0,
                            cudaMemcpyDeviceToDevice, 0);
    cudaMemcpyToSymbolAsync(c_w2, d_in[4], 256 * sizeof(float), 0,
                            cudaMemcpyDeviceToDevice, 0);
    cudaMemcpyToSymbolAsync(c_b2, d_in[5], 16  * sizeof(float), 0,
                            cudaMemcpyDeviceToDevice, 0);

    // 0) sniff index dtype
    detect_kernel<<<1, 1>>>((const unsigned long long*)ei);

    // 1) zero accumulator
    {
        int threads = 256;
        int blocks = (n_nodes + threads - 1) / threads;
        zero_lf_kernel<<<blocks, threads>>>(n_nodes);
    }

    // 2) edge scatter: 8 edges/thread
    {
        int n_oct = (n_edges + 7) >> 3;
        int threads = 256;
        int blocks = (n_oct + threads - 1) / threads;
        edge_kernel<<<blocks, threads>>>(x, ei, n_edges);
    }

    // 3) fused 2-layer MLP
    {
        int threads = 128;
        int blocks = (n_nodes + threads - 1) / threads;
        mlp_kernel<<<blocks, threads>>>(x, out, n_nodes);
    }
}